// round 4
// baseline (speedup 1.0000x reference)
#include <cuda_runtime.h>
#include <cuda_bf16.h>
#include <cstdint>

// Problem constants (Head_84533546320520)
#define BATCH 8
#define SEQ   2048
#define DEMB  1024
#define HEAD  64
#define NROWS (BATCH * SEQ)   // 16384
#define SCALE 0.125f          // HEAD^-0.5

// Scratch for projected q/k/v: [B*S, 64] each, fp32
__device__ float g_qp[NROWS * HEAD];
__device__ float g_kp[NROWS * HEAD];
__device__ float g_vp[NROWS * HEAD];

// ===========================================================================
// mma.sync helpers (sm_80-era PTX; no sm_103a-gated features)
// ===========================================================================
__device__ __forceinline__ uint32_t smem_to_u32(const void* p) {
    uint32_t a;
    asm("{ .reg .u64 t; cvta.to.shared.u64 t, %1; cvt.u32.u64 %0, t; }"
        : "=r"(a) : "l"(p));
    return a;
}

__device__ __forceinline__ void ldsm_x4(uint32_t* r, uint32_t addr) {
    asm volatile("ldmatrix.sync.aligned.m8n8.x4.shared.b16 {%0,%1,%2,%3}, [%4];"
        : "=r"(r[0]), "=r"(r[1]), "=r"(r[2]), "=r"(r[3]) : "r"(addr));
}
__device__ __forceinline__ void ldsm_x4_trans(uint32_t* r, uint32_t addr) {
    asm volatile("ldmatrix.sync.aligned.m8n8.x4.trans.shared.b16 {%0,%1,%2,%3}, [%4];"
        : "=r"(r[0]), "=r"(r[1]), "=r"(r[2]), "=r"(r[3]) : "r"(addr));
}
// D += A(16x16 row) * B(16x8 col), bf16 in, f32 accum
__device__ __forceinline__ void mma_bf16(float* d, const uint32_t* a, const uint32_t* b) {
    asm volatile(
        "mma.sync.aligned.m16n8k16.row.col.f32.bf16.bf16.f32 "
        "{%0,%1,%2,%3}, {%4,%5,%6,%7}, {%8,%9}, {%0,%1,%2,%3};"
        : "+f"(d[0]), "+f"(d[1]), "+f"(d[2]), "+f"(d[3])
        : "r"(a[0]), "r"(a[1]), "r"(a[2]), "r"(a[3]), "r"(b[0]), "r"(b[1]));
}

// ===========================================================================
// Kernel 1: projections via mma.sync bf16 2-split (hh + hl + lh).
// grid = (NROWS/128, 3), block = 256 (8 warps; warp w -> rows w*16..w*16+15).
// C[128,64] = X[128,1024] @ W[1024,64], K chunked by 64.
// ===========================================================================
#define KC 64
#define NCH (DEMB / KC)          // 16
#define APAD 72                  // row stride (bf16 elems): 144B, conflict-free LDSM
// smem: AsHi[128*72] AsLo[128*72] BsHi[64*72] BsLo[64*72]  (bf16) = 55296 B
#define PROJ_SMEM ((2 * 128 * APAD + 2 * 64 * APAD) * 2)

__global__ __launch_bounds__(256) void proj_mma_kernel(
    const float* __restrict__ q, const float* __restrict__ k,
    const float* __restrict__ v,
    const float* __restrict__ Wq, const float* __restrict__ Wk,
    const float* __restrict__ Wv)
{
    extern __shared__ __align__(16) __nv_bfloat16 smb[];
    __nv_bfloat16* AsHi = smb;
    __nv_bfloat16* AsLo = AsHi + 128 * APAD;
    __nv_bfloat16* BsHi = AsLo + 128 * APAD;
    __nv_bfloat16* BsLo = BsHi + 64 * APAD;
    const uint32_t aHiB = smem_to_u32(AsHi);
    const uint32_t aLoB = smem_to_u32(AsLo);
    const uint32_t bHiB = smem_to_u32(BsHi);
    const uint32_t bLoB = smem_to_u32(BsLo);

    const int which = blockIdx.y;
    const float* __restrict__ X = (which == 0) ? q : (which == 1) ? k : v;
    const float* __restrict__ W = (which == 0) ? Wq : (which == 1) ? Wk : Wv;
    float* __restrict__ out     = (which == 0) ? g_qp : (which == 1) ? g_kp : g_vp;

    const int tid = threadIdx.x;
    const int wid = tid >> 5;
    const int lane = tid & 31;
    const int l16 = lane & 15;
    const int hi8 = (lane >> 4) << 3;   // 0 or 8
    const int row0 = blockIdx.x * 128;
    const int m0 = wid * 16;

    float acc[8][4] = {};   // 8 n-frags (n = j*8) x 4

    for (int c = 0; c < NCH; c++) {
        const int k0 = c * KC;
        if (c > 0) __syncthreads();   // previous MMAs done before overwrite

        // --- convert A chunk: X[row0+r][k0+cg*4..+3] -> hi/lo bf16 ---
        #pragma unroll
        for (int i = 0; i < 8; i++) {
            int idx = tid + i * 256;       // 0..2047
            int r   = idx >> 4;            // 0..127
            int cg  = idx & 15;            // 0..15
            float4 t = *reinterpret_cast<const float4*>(
                X + (size_t)(row0 + r) * DEMB + k0 + cg * 4);
            __nv_bfloat162 h01 = __float22bfloat162_rn(make_float2(t.x, t.y));
            __nv_bfloat162 h23 = __float22bfloat162_rn(make_float2(t.z, t.w));
            float2 f01 = __bfloat1622float2(h01);
            float2 f23 = __bfloat1622float2(h23);
            __nv_bfloat162 l01 = __float22bfloat162_rn(make_float2(t.x - f01.x, t.y - f01.y));
            __nv_bfloat162 l23 = __float22bfloat162_rn(make_float2(t.z - f23.x, t.w - f23.y));
            int o = r * APAD + cg * 4;
            *reinterpret_cast<__nv_bfloat162*>(&AsHi[o])     = h01;
            *reinterpret_cast<__nv_bfloat162*>(&AsHi[o + 2]) = h23;
            *reinterpret_cast<__nv_bfloat162*>(&AsLo[o])     = l01;
            *reinterpret_cast<__nv_bfloat162*>(&AsLo[o + 2]) = l23;
        }

        // --- convert B chunk: W[k0+kk][ng*4..+3] -> Bs[kk][n] hi/lo ---
        #pragma unroll
        for (int i = 0; i < 4; i++) {
            int idx = tid + i * 256;       // 0..1023
            int kk  = idx >> 4;            // 0..63
            int ng  = idx & 15;            // 0..15
            float4 t = *reinterpret_cast<const float4*>(
                W + (size_t)(k0 + kk) * HEAD + ng * 4);
            __nv_bfloat162 h01 = __float22bfloat162_rn(make_float2(t.x, t.y));
            __nv_bfloat162 h23 = __float22bfloat162_rn(make_float2(t.z, t.w));
            float2 f01 = __bfloat1622float2(h01);
            float2 f23 = __bfloat1622float2(h23);
            __nv_bfloat162 l01 = __float22bfloat162_rn(make_float2(t.x - f01.x, t.y - f01.y));
            __nv_bfloat162 l23 = __float22bfloat162_rn(make_float2(t.z - f23.x, t.w - f23.y));
            int o = kk * APAD + ng * 4;
            *reinterpret_cast<__nv_bfloat162*>(&BsHi[o])     = h01;
            *reinterpret_cast<__nv_bfloat162*>(&BsHi[o + 2]) = h23;
            *reinterpret_cast<__nv_bfloat162*>(&BsLo[o])     = l01;
            *reinterpret_cast<__nv_bfloat162*>(&BsLo[o + 2]) = l23;
        }
        __syncthreads();

        // --- MMA over the 64-deep chunk: 4 k16 steps ---
        #pragma unroll
        for (int kk = 0; kk < 4; kk++) {
            uint32_t a_hi[4], a_lo[4];
            uint32_t aoff = (uint32_t)(((m0 + l16) * APAD + kk * 16 + hi8) * 2);
            ldsm_x4(a_hi, aHiB + aoff);
            ldsm_x4(a_lo, aLoB + aoff);
            #pragma unroll
            for (int nb = 0; nb < 4; nb++) {   // two n8 frags per ldsm.x4.trans
                uint32_t bh[4], bl[4];
                uint32_t boff = (uint32_t)(((kk * 16 + l16) * APAD + nb * 16 + hi8) * 2);
                ldsm_x4_trans(bh, bHiB + boff);
                ldsm_x4_trans(bl, bLoB + boff);
                mma_bf16(acc[2 * nb + 0], a_hi, bh + 0);
                mma_bf16(acc[2 * nb + 1], a_hi, bh + 2);
                mma_bf16(acc[2 * nb + 0], a_hi, bl + 0);
                mma_bf16(acc[2 * nb + 1], a_hi, bl + 2);
                mma_bf16(acc[2 * nb + 0], a_lo, bh + 0);
                mma_bf16(acc[2 * nb + 1], a_lo, bh + 2);
            }
        }
    }

    // --- epilogue: C fragment layout m16n8 -> out[row][n] ---
    const int r = lane >> 2;
    const int cc = (lane & 3) * 2;
    float* o0 = out + (size_t)(row0 + m0 + r) * HEAD;
    float* o1 = out + (size_t)(row0 + m0 + r + 8) * HEAD;
    #pragma unroll
    for (int j = 0; j < 8; j++) {
        *reinterpret_cast<float2*>(o0 + j * 8 + cc) = make_float2(acc[j][0], acc[j][1]);
        *reinterpret_cast<float2*>(o1 + j * 8 + cc) = make_float2(acc[j][2], acc[j][3]);
    }
}

// ---------------------------------------------------------------------------
// Kernel 2: flash attention (UNCHANGED from passing round).
// grid = (32, 8), block 256. Mask is int32 (nonzero = attend).
// ---------------------------------------------------------------------------
__global__ __launch_bounds__(256) void attn_kernel(
    const int* __restrict__ mask, float* __restrict__ out)
{
    const int b  = blockIdx.y;
    const int q0 = blockIdx.x * 64;
    const float* __restrict__ qp = g_qp + (size_t)b * SEQ * HEAD;
    const float* __restrict__ kp = g_kp + (size_t)b * SEQ * HEAD;
    const float* __restrict__ vp = g_vp + (size_t)b * SEQ * HEAD;

    extern __shared__ float sm[];
    float* Qs = sm;                 // [64 h][68 q]
    float* Ks = Qs + 64 * 68;       // [64 h][68 k]
    float* Vs = Ks + 64 * 68;       // [64 k][64 h]
    float* Ps = Vs + 64 * 64;       // [64 k][68 q]
    __shared__ float biasS[64];

    const int tid = threadIdx.x;
    const int tx = tid & 15;
    const int ty = tid >> 4;

    #pragma unroll
    for (int i = 0; i < 4; i++) {
        int idx = tid + i * 256;
        int qr  = idx >> 4;
        int hq  = idx & 15;
        float4 t = *reinterpret_cast<const float4*>(qp + (size_t)(q0 + qr) * HEAD + hq * 4);
        Qs[(hq * 4 + 0) * 68 + qr] = t.x * SCALE;
        Qs[(hq * 4 + 1) * 68 + qr] = t.y * SCALE;
        Qs[(hq * 4 + 2) * 68 + qr] = t.z * SCALE;
        Qs[(hq * 4 + 3) * 68 + qr] = t.w * SCALE;
    }

    const float NEG_INF = __int_as_float(0xff800000);
    float m[4] = {NEG_INF, NEG_INF, NEG_INF, NEG_INF};
    float l[4] = {0.f, 0.f, 0.f, 0.f};
    float o[4][4] = {};

    for (int kt = 0; kt < SEQ / 64; kt++) {
        const int k0 = kt * 64;

        #pragma unroll
        for (int i = 0; i < 4; i++) {
            int idx = tid + i * 256;
            int kr  = idx >> 4;
            int hq  = idx & 15;
            float4 t = *reinterpret_cast<const float4*>(kp + (size_t)(k0 + kr) * HEAD + hq * 4);
            Ks[(hq * 4 + 0) * 68 + kr] = t.x;
            Ks[(hq * 4 + 1) * 68 + kr] = t.y;
            Ks[(hq * 4 + 2) * 68 + kr] = t.z;
            Ks[(hq * 4 + 3) * 68 + kr] = t.w;
            float4 u = *reinterpret_cast<const float4*>(vp + (size_t)(k0 + kr) * HEAD + hq * 4);
            *reinterpret_cast<float4*>(&Vs[kr * 64 + hq * 4]) = u;
        }
        if (tid < 64)
            biasS[tid] = (mask[(size_t)b * SEQ + k0 + tid] != 0) ? 0.f : -1e30f;
        __syncthreads();

        float s[4][4] = {};
        #pragma unroll 8
        for (int h = 0; h < 64; h++) {
            float4 a = *reinterpret_cast<const float4*>(&Qs[h * 68 + ty * 4]);
            float4 kb = *reinterpret_cast<const float4*>(&Ks[h * 68 + tx * 4]);
            s[0][0] += a.x * kb.x; s[0][1] += a.x * kb.y; s[0][2] += a.x * kb.z; s[0][3] += a.x * kb.w;
            s[1][0] += a.y * kb.x; s[1][1] += a.y * kb.y; s[1][2] += a.y * kb.z; s[1][3] += a.y * kb.w;
            s[2][0] += a.z * kb.x; s[2][1] += a.z * kb.y; s[2][2] += a.z * kb.z; s[2][3] += a.z * kb.w;
            s[3][0] += a.w * kb.x; s[3][1] += a.w * kb.y; s[3][2] += a.w * kb.z; s[3][3] += a.w * kb.w;
        }

        #pragma unroll
        for (int i = 0; i < 4; i++) {
            float p0 = s[i][0] + biasS[tx * 4 + 0];
            float p1 = s[i][1] + biasS[tx * 4 + 1];
            float p2 = s[i][2] + biasS[tx * 4 + 2];
            float p3 = s[i][3] + biasS[tx * 4 + 3];
            float mx = fmaxf(fmaxf(p0, p1), fmaxf(p2, p3));
            #pragma unroll
            for (int off = 1; off < 16; off <<= 1)
                mx = fmaxf(mx, __shfl_xor_sync(0xffffffffu, mx, off));
            float m_new = fmaxf(m[i], mx);
            float alpha = __expf(m[i] - m_new);
            p0 = __expf(p0 - m_new);
            p1 = __expf(p1 - m_new);
            p2 = __expf(p2 - m_new);
            p3 = __expf(p3 - m_new);
            float rs = p0 + p1 + p2 + p3;
            #pragma unroll
            for (int off = 1; off < 16; off <<= 1)
                rs += __shfl_xor_sync(0xffffffffu, rs, off);
            l[i] = l[i] * alpha + rs;
            m[i] = m_new;
            o[i][0] *= alpha; o[i][1] *= alpha; o[i][2] *= alpha; o[i][3] *= alpha;
            Ps[(tx * 4 + 0) * 68 + ty * 4 + i] = p0;
            Ps[(tx * 4 + 1) * 68 + ty * 4 + i] = p1;
            Ps[(tx * 4 + 2) * 68 + ty * 4 + i] = p2;
            Ps[(tx * 4 + 3) * 68 + ty * 4 + i] = p3;
        }
        __syncthreads();

        #pragma unroll 8
        for (int kk = 0; kk < 64; kk++) {
            float4 a = *reinterpret_cast<const float4*>(&Ps[kk * 68 + ty * 4]);
            float4 vb = *reinterpret_cast<const float4*>(&Vs[kk * 64 + tx * 4]);
            o[0][0] += a.x * vb.x; o[0][1] += a.x * vb.y; o[0][2] += a.x * vb.z; o[0][3] += a.x * vb.w;
            o[1][0] += a.y * vb.x; o[1][1] += a.y * vb.y; o[1][2] += a.y * vb.z; o[1][3] += a.y * vb.w;
            o[2][0] += a.z * vb.x; o[2][1] += a.z * vb.y; o[2][2] += a.z * vb.z; o[2][3] += a.z * vb.w;
            o[3][0] += a.w * vb.x; o[3][1] += a.w * vb.y; o[3][2] += a.w * vb.z; o[3][3] += a.w * vb.w;
        }
        __syncthreads();
    }

    #pragma unroll
    for (int i = 0; i < 4; i++) {
        float inv = 1.0f / l[i];
        float4 r = make_float4(o[i][0] * inv, o[i][1] * inv, o[i][2] * inv, o[i][3] * inv);
        *reinterpret_cast<float4*>(out + (size_t)(b * SEQ + q0 + ty * 4 + i) * HEAD + tx * 4) = r;
    }
}

// ---------------------------------------------------------------------------
extern "C" void kernel_launch(void* const* d_in, const int* in_sizes, int n_in,
                              void* d_out, int out_size)
{
    // bind by element count: 16777216 -> q,k,v ; 65536 -> Wq,Wk,Wv ; 16384 -> mask
    const void* big[3]   = {0, 0, 0};
    const void* small[3] = {0, 0, 0};
    const void* mk = 0;
    int nb = 0, ns = 0;
    for (int i = 0; i < n_in; i++) {
        if (in_sizes[i] == NROWS * DEMB)      { if (nb < 3) big[nb++] = d_in[i]; }
        else if (in_sizes[i] == DEMB * HEAD)  { if (ns < 3) small[ns++] = d_in[i]; }
        else if (in_sizes[i] == BATCH * SEQ)  { mk = d_in[i]; }
    }
    const float* q  = (const float*)big[0];
    const float* k  = (const float*)big[1];
    const float* v  = (const float*)big[2];
    const float* Wq = (const float*)small[0];
    const float* Wk = (const float*)small[1];
    const float* Wv = (const float*)small[2];
    const int*   mask = (const int*)mk;
    float* out = (float*)d_out;

    static bool attr_set = false;
    const int attn_smem = (64 * 68 * 2 + 64 * 64 + 64 * 68) * (int)sizeof(float);
    if (!attr_set) {
        cudaFuncSetAttribute(proj_mma_kernel, cudaFuncAttributeMaxDynamicSharedMemorySize, PROJ_SMEM);
        cudaFuncSetAttribute(attn_kernel, cudaFuncAttributeMaxDynamicSharedMemorySize, attn_smem);
        attr_set = true;
    }

    proj_mma_kernel<<<dim3(NROWS / 128, 3), 256, PROJ_SMEM>>>(q, k, v, Wq, Wk, Wv);
    attn_kernel<<<dim3(SEQ / 64, BATCH), 256, attn_smem>>>(mask, out);
}

// round 5
// speedup vs baseline: 3.5536x; 3.5536x over previous
#include <cuda_runtime.h>
#include <cuda_bf16.h>
#include <cstdint>

// Problem constants (Head_84533546320520)
#define BATCH 8
#define SEQ   2048
#define DEMB  1024
#define HEAD  64
#define NROWS (BATCH * SEQ)   // 16384
#define SCALE 0.125f          // HEAD^-0.5

// Scratch for projected q/k/v: [B*S, 64] each, fp32
__device__ float g_qp[NROWS * HEAD];
__device__ float g_kp[NROWS * HEAD];
__device__ float g_vp[NROWS * HEAD];

// ===========================================================================
// mma.sync helpers (sm_80-era PTX; no sm_103a-gated features)
// ===========================================================================
__device__ __forceinline__ uint32_t smem_to_u32(const void* p) {
    uint32_t a;
    asm("{ .reg .u64 t; cvta.to.shared.u64 t, %1; cvt.u32.u64 %0, t; }"
        : "=r"(a) : "l"(p));
    return a;
}
__device__ __forceinline__ void ldsm_x4(uint32_t* r, uint32_t addr) {
    asm volatile("ldmatrix.sync.aligned.m8n8.x4.shared.b16 {%0,%1,%2,%3}, [%4];"
        : "=r"(r[0]), "=r"(r[1]), "=r"(r[2]), "=r"(r[3]) : "r"(addr));
}
__device__ __forceinline__ void ldsm_x4_trans(uint32_t* r, uint32_t addr) {
    asm volatile("ldmatrix.sync.aligned.m8n8.x4.trans.shared.b16 {%0,%1,%2,%3}, [%4];"
        : "=r"(r[0]), "=r"(r[1]), "=r"(r[2]), "=r"(r[3]) : "r"(addr));
}
// D += A(16x16 row) * B(16x8 col), bf16 in, f32 accum
__device__ __forceinline__ void mma_bf16(float* d, const uint32_t* a, const uint32_t* b) {
    asm volatile(
        "mma.sync.aligned.m16n8k16.row.col.f32.bf16.bf16.f32 "
        "{%0,%1,%2,%3}, {%4,%5,%6,%7}, {%8,%9}, {%0,%1,%2,%3};"
        : "+f"(d[0]), "+f"(d[1]), "+f"(d[2]), "+f"(d[3])
        : "r"(a[0]), "r"(a[1]), "r"(a[2]), "r"(a[3]), "r"(b[0]), "r"(b[1]));
}
// split two floats into packed bf16x2 hi + residual lo
__device__ __forceinline__ void split2(float x, float y, uint32_t& h, uint32_t& l) {
    __nv_bfloat162 hb = __float22bfloat162_rn(make_float2(x, y));
    float2 hf = __bfloat1622float2(hb);
    __nv_bfloat162 lb = __float22bfloat162_rn(make_float2(x - hf.x, y - hf.y));
    h = *reinterpret_cast<uint32_t*>(&hb);
    l = *reinterpret_cast<uint32_t*>(&lb);
}

// ===========================================================================
// Kernel 1: projections via mma.sync bf16 2-split (UNCHANGED, validated).
// ===========================================================================
#define KC 64
#define NCH (DEMB / KC)          // 16
#define APAD 72
#define PROJ_SMEM ((2 * 128 * APAD + 2 * 64 * APAD) * 2)

__global__ __launch_bounds__(256) void proj_mma_kernel(
    const float* __restrict__ q, const float* __restrict__ k,
    const float* __restrict__ v,
    const float* __restrict__ Wq, const float* __restrict__ Wk,
    const float* __restrict__ Wv)
{
    extern __shared__ __align__(16) __nv_bfloat16 smb[];
    __nv_bfloat16* AsHi = smb;
    __nv_bfloat16* AsLo = AsHi + 128 * APAD;
    __nv_bfloat16* BsHi = AsLo + 128 * APAD;
    __nv_bfloat16* BsLo = BsHi + 64 * APAD;
    const uint32_t aHiB = smem_to_u32(AsHi);
    const uint32_t aLoB = smem_to_u32(AsLo);
    const uint32_t bHiB = smem_to_u32(BsHi);
    const uint32_t bLoB = smem_to_u32(BsLo);

    const int which = blockIdx.y;
    const float* __restrict__ X = (which == 0) ? q : (which == 1) ? k : v;
    const float* __restrict__ W = (which == 0) ? Wq : (which == 1) ? Wk : Wv;
    float* __restrict__ out     = (which == 0) ? g_qp : (which == 1) ? g_kp : g_vp;

    const int tid = threadIdx.x;
    const int wid = tid >> 5;
    const int lane = tid & 31;
    const int l16 = lane & 15;
    const int hi8 = (lane >> 4) << 3;
    const int row0 = blockIdx.x * 128;
    const int m0 = wid * 16;

    float acc[8][4] = {};

    for (int c = 0; c < NCH; c++) {
        const int k0 = c * KC;
        if (c > 0) __syncthreads();

        #pragma unroll
        for (int i = 0; i < 8; i++) {
            int idx = tid + i * 256;
            int r   = idx >> 4;
            int cg  = idx & 15;
            float4 t = *reinterpret_cast<const float4*>(
                X + (size_t)(row0 + r) * DEMB + k0 + cg * 4);
            __nv_bfloat162 h01 = __float22bfloat162_rn(make_float2(t.x, t.y));
            __nv_bfloat162 h23 = __float22bfloat162_rn(make_float2(t.z, t.w));
            float2 f01 = __bfloat1622float2(h01);
            float2 f23 = __bfloat1622float2(h23);
            __nv_bfloat162 l01 = __float22bfloat162_rn(make_float2(t.x - f01.x, t.y - f01.y));
            __nv_bfloat162 l23 = __float22bfloat162_rn(make_float2(t.z - f23.x, t.w - f23.y));
            int o = r * APAD + cg * 4;
            *reinterpret_cast<__nv_bfloat162*>(&AsHi[o])     = h01;
            *reinterpret_cast<__nv_bfloat162*>(&AsHi[o + 2]) = h23;
            *reinterpret_cast<__nv_bfloat162*>(&AsLo[o])     = l01;
            *reinterpret_cast<__nv_bfloat162*>(&AsLo[o + 2]) = l23;
        }
        #pragma unroll
        for (int i = 0; i < 4; i++) {
            int idx = tid + i * 256;
            int kk  = idx >> 4;
            int ng  = idx & 15;
            float4 t = *reinterpret_cast<const float4*>(
                W + (size_t)(k0 + kk) * HEAD + ng * 4);
            __nv_bfloat162 h01 = __float22bfloat162_rn(make_float2(t.x, t.y));
            __nv_bfloat162 h23 = __float22bfloat162_rn(make_float2(t.z, t.w));
            float2 f01 = __bfloat1622float2(h01);
            float2 f23 = __bfloat1622float2(h23);
            __nv_bfloat162 l01 = __float22bfloat162_rn(make_float2(t.x - f01.x, t.y - f01.y));
            __nv_bfloat162 l23 = __float22bfloat162_rn(make_float2(t.z - f23.x, t.w - f23.y));
            int o = kk * APAD + ng * 4;
            *reinterpret_cast<__nv_bfloat162*>(&BsHi[o])     = h01;
            *reinterpret_cast<__nv_bfloat162*>(&BsHi[o + 2]) = h23;
            *reinterpret_cast<__nv_bfloat162*>(&BsLo[o])     = l01;
            *reinterpret_cast<__nv_bfloat162*>(&BsLo[o + 2]) = l23;
        }
        __syncthreads();

        #pragma unroll
        for (int kk = 0; kk < 4; kk++) {
            uint32_t a_hi[4], a_lo[4];
            uint32_t aoff = (uint32_t)(((m0 + l16) * APAD + kk * 16 + hi8) * 2);
            ldsm_x4(a_hi, aHiB + aoff);
            ldsm_x4(a_lo, aLoB + aoff);
            #pragma unroll
            for (int nb = 0; nb < 4; nb++) {
                uint32_t bh[4], bl[4];
                uint32_t boff = (uint32_t)(((kk * 16 + l16) * APAD + nb * 16 + hi8) * 2);
                ldsm_x4_trans(bh, bHiB + boff);
                ldsm_x4_trans(bl, bLoB + boff);
                mma_bf16(acc[2 * nb + 0], a_hi, bh + 0);
                mma_bf16(acc[2 * nb + 1], a_hi, bh + 2);
                mma_bf16(acc[2 * nb + 0], a_hi, bl + 0);
                mma_bf16(acc[2 * nb + 1], a_hi, bl + 2);
                mma_bf16(acc[2 * nb + 0], a_lo, bh + 0);
                mma_bf16(acc[2 * nb + 1], a_lo, bh + 2);
            }
        }
    }

    const int r = lane >> 2;
    const int cc = (lane & 3) * 2;
    float* o0 = out + (size_t)(row0 + m0 + r) * HEAD;
    float* o1 = out + (size_t)(row0 + m0 + r + 8) * HEAD;
    #pragma unroll
    for (int j = 0; j < 8; j++) {
        *reinterpret_cast<float2*>(o0 + j * 8 + cc) = make_float2(acc[j][0], acc[j][1]);
        *reinterpret_cast<float2*>(o1 + j * 8 + cc) = make_float2(acc[j][2], acc[j][3]);
    }
}

// ===========================================================================
// Kernel 2: flash attention via mma.sync bf16 2-split.
// grid = (SEQ/64, BATCH), block = 128 (4 warps; warp w -> q rows w*16..+15).
// K and V tiles stored STRAIGHT [key][h] (no transposed smem writes):
//   S B-frags: non-trans ldsm with custom lane map on [key][h]
//   PV B-frags: trans ldsm (validated recipe) on [key][h]
//   P stays in registers (C-frag -> A-frag identity mapping).
// ===========================================================================
#define AP 72
#define ATTN_SMEM (4 * 64 * AP * 2 + 256)   // 37120 B

__global__ __launch_bounds__(128) void attn_mma_kernel(
    const int* __restrict__ mask, float* __restrict__ out)
{
    extern __shared__ __align__(16) __nv_bfloat16 smb[];
    __nv_bfloat16* KsHi = smb;                 // [64 key][AP h]
    __nv_bfloat16* KsLo = smb + 64 * AP;
    __nv_bfloat16* VsHi = smb + 2 * 64 * AP;   // [64 key][AP h]
    __nv_bfloat16* VsLo = smb + 3 * 64 * AP;
    float* biasS = reinterpret_cast<float*>(smb + 4 * 64 * AP);

    const uint32_t ksHiB = smem_to_u32(KsHi);
    const uint32_t ksLoB = smem_to_u32(KsLo);
    const uint32_t vsHiB = smem_to_u32(VsHi);
    const uint32_t vsLoB = smem_to_u32(VsLo);

    const int b  = blockIdx.y;
    const int q0 = blockIdx.x * 64;
    const float* __restrict__ qp = g_qp + (size_t)b * SEQ * HEAD;
    const float* __restrict__ kp = g_kp + (size_t)b * SEQ * HEAD;
    const float* __restrict__ vp = g_vp + (size_t)b * SEQ * HEAD;

    const int tid  = threadIdx.x;
    const int wid  = tid >> 5;
    const int lane = tid & 31;
    const int l16  = lane & 15;
    const int hi8  = (lane >> 4) << 3;
    const int m0   = wid * 16;
    const int c2   = (lane & 3) * 2;

    // lane map for S-phase B-frag ldsm (non-trans on straight [key][h]):
    // matrices: (key0-7,h+0),(key0-7,h+8),(key8-15,h+0),(key8-15,h+8)
    const int krow = (lane & 7) + ((lane & 16) >> 1);  // 0..15
    const int hcol = (lane & 8);                        // 0 or 8

    // ---- stage Q (pre-scaled) hi/lo into smem overlay, then frags ----
    {
        __nv_bfloat16* QHi = smb;            // [64 q][AP h]
        __nv_bfloat16* QLo = smb + 64 * AP;
        #pragma unroll
        for (int i = 0; i < 8; i++) {
            int idx = tid + i * 128;          // 0..1023
            int r = idx >> 4, cg = idx & 15;
            float4 t = *reinterpret_cast<const float4*>(qp + (size_t)(q0 + r) * HEAD + cg * 4);
            t.x *= SCALE; t.y *= SCALE; t.z *= SCALE; t.w *= SCALE;
            __nv_bfloat162 h01 = __float22bfloat162_rn(make_float2(t.x, t.y));
            __nv_bfloat162 h23 = __float22bfloat162_rn(make_float2(t.z, t.w));
            float2 f01 = __bfloat1622float2(h01);
            float2 f23 = __bfloat1622float2(h23);
            __nv_bfloat162 l01 = __float22bfloat162_rn(make_float2(t.x - f01.x, t.y - f01.y));
            __nv_bfloat162 l23 = __float22bfloat162_rn(make_float2(t.z - f23.x, t.w - f23.y));
            int o4 = r * AP + cg * 4;
            *reinterpret_cast<__nv_bfloat162*>(&QHi[o4])     = h01;
            *reinterpret_cast<__nv_bfloat162*>(&QHi[o4 + 2]) = h23;
            *reinterpret_cast<__nv_bfloat162*>(&QLo[o4])     = l01;
            *reinterpret_cast<__nv_bfloat162*>(&QLo[o4 + 2]) = l23;
        }
    }
    __syncthreads();
    uint32_t qh[4][4], qlr[4][4];
    {
        const uint32_t qHiB = smem_to_u32(smb);
        const uint32_t qLoB = qHiB + 64 * AP * 2;
        #pragma unroll
        for (int kh = 0; kh < 4; kh++) {
            uint32_t aoff = (uint32_t)(((m0 + l16) * AP + kh * 16 + hi8) * 2);
            ldsm_x4(qh[kh],  qHiB + aoff);
            ldsm_x4(qlr[kh], qLoB + aoff);
        }
    }
    __syncthreads();

    const float NEG_INF = __int_as_float(0xff800000);
    float mR0 = NEG_INF, mR1 = NEG_INF, lS0 = 0.f, lS1 = 0.f;
    float o[8][4] = {};

    for (int kt = 0; kt < SEQ / 64; kt++) {
        const int k0 = kt * 64;

        // load + split K, V tiles (straight [key][h], conflict-free)
        #pragma unroll
        for (int i = 0; i < 8; i++) {
            int idx = tid + i * 128;
            int r = idx >> 4, cg = idx & 15;
            int o4 = r * AP + cg * 4;
            float4 t = *reinterpret_cast<const float4*>(kp + (size_t)(k0 + r) * HEAD + cg * 4);
            {
                __nv_bfloat162 h01 = __float22bfloat162_rn(make_float2(t.x, t.y));
                __nv_bfloat162 h23 = __float22bfloat162_rn(make_float2(t.z, t.w));
                float2 f01 = __bfloat1622float2(h01);
                float2 f23 = __bfloat1622float2(h23);
                __nv_bfloat162 l01 = __float22bfloat162_rn(make_float2(t.x - f01.x, t.y - f01.y));
                __nv_bfloat162 l23 = __float22bfloat162_rn(make_float2(t.z - f23.x, t.w - f23.y));
                *reinterpret_cast<__nv_bfloat162*>(&KsHi[o4])     = h01;
                *reinterpret_cast<__nv_bfloat162*>(&KsHi[o4 + 2]) = h23;
                *reinterpret_cast<__nv_bfloat162*>(&KsLo[o4])     = l01;
                *reinterpret_cast<__nv_bfloat162*>(&KsLo[o4 + 2]) = l23;
            }
            float4 u = *reinterpret_cast<const float4*>(vp + (size_t)(k0 + r) * HEAD + cg * 4);
            {
                __nv_bfloat162 h01 = __float22bfloat162_rn(make_float2(u.x, u.y));
                __nv_bfloat162 h23 = __float22bfloat162_rn(make_float2(u.z, u.w));
                float2 f01 = __bfloat1622float2(h01);
                float2 f23 = __bfloat1622float2(h23);
                __nv_bfloat162 l01 = __float22bfloat162_rn(make_float2(u.x - f01.x, u.y - f01.y));
                __nv_bfloat162 l23 = __float22bfloat162_rn(make_float2(u.z - f23.x, u.w - f23.y));
                *reinterpret_cast<__nv_bfloat162*>(&VsHi[o4])     = h01;
                *reinterpret_cast<__nv_bfloat162*>(&VsHi[o4 + 2]) = h23;
                *reinterpret_cast<__nv_bfloat162*>(&VsLo[o4])     = l01;
                *reinterpret_cast<__nv_bfloat162*>(&VsLo[o4 + 2]) = l23;
            }
        }
        if (tid < 64)
            biasS[tid] = (mask[(size_t)b * SEQ + k0 + tid] != 0) ? 0.f : -1e30f;
        __syncthreads();

        // ---- S = Q @ K^T ----
        float s[8][4] = {};
        #pragma unroll
        for (int kh = 0; kh < 4; kh++) {
            #pragma unroll
            for (int nb = 0; nb < 4; nb++) {
                uint32_t bh[4], bl[4];
                uint32_t boff = (uint32_t)(((nb * 16 + krow) * AP + kh * 16 + hcol) * 2);
                ldsm_x4(bh, ksHiB + boff);
                ldsm_x4(bl, ksLoB + boff);
                mma_bf16(s[2 * nb],     qh[kh],  bh);
                mma_bf16(s[2 * nb + 1], qh[kh],  bh + 2);
                mma_bf16(s[2 * nb],     qh[kh],  bl);
                mma_bf16(s[2 * nb + 1], qh[kh],  bl + 2);
                mma_bf16(s[2 * nb],     qlr[kh], bh);
                mma_bf16(s[2 * nb + 1], qlr[kh], bh + 2);
            }
        }

        // ---- online softmax on C-frags (rows r=lane>>2 and r+8) ----
        float mx0 = NEG_INF, mx1 = NEG_INF;
        #pragma unroll
        for (int j = 0; j < 8; j++) {
            float2 bv = *reinterpret_cast<float2*>(&biasS[j * 8 + c2]);
            s[j][0] += bv.x; s[j][1] += bv.y; s[j][2] += bv.x; s[j][3] += bv.y;
            mx0 = fmaxf(mx0, fmaxf(s[j][0], s[j][1]));
            mx1 = fmaxf(mx1, fmaxf(s[j][2], s[j][3]));
        }
        mx0 = fmaxf(mx0, __shfl_xor_sync(0xffffffffu, mx0, 1));
        mx0 = fmaxf(mx0, __shfl_xor_sync(0xffffffffu, mx0, 2));
        mx1 = fmaxf(mx1, __shfl_xor_sync(0xffffffffu, mx1, 1));
        mx1 = fmaxf(mx1, __shfl_xor_sync(0xffffffffu, mx1, 2));
        float mn0 = fmaxf(mR0, mx0), mn1 = fmaxf(mR1, mx1);
        float a0 = __expf(mR0 - mn0), a1 = __expf(mR1 - mn1);
        float sm0 = 0.f, sm1 = 0.f;
        #pragma unroll
        for (int j = 0; j < 8; j++) {
            s[j][0] = __expf(s[j][0] - mn0);
            s[j][1] = __expf(s[j][1] - mn0);
            s[j][2] = __expf(s[j][2] - mn1);
            s[j][3] = __expf(s[j][3] - mn1);
            sm0 += s[j][0] + s[j][1];
            sm1 += s[j][2] + s[j][3];
        }
        sm0 += __shfl_xor_sync(0xffffffffu, sm0, 1);
        sm0 += __shfl_xor_sync(0xffffffffu, sm0, 2);
        sm1 += __shfl_xor_sync(0xffffffffu, sm1, 1);
        sm1 += __shfl_xor_sync(0xffffffffu, sm1, 2);
        lS0 = lS0 * a0 + sm0; lS1 = lS1 * a1 + sm1;
        mR0 = mn0; mR1 = mn1;
        #pragma unroll
        for (int j = 0; j < 8; j++) {
            o[j][0] *= a0; o[j][1] *= a0; o[j][2] *= a1; o[j][3] *= a1;
        }

        // ---- O += P @ V  (P frags built in-register from C-frags) ----
        #pragma unroll
        for (int kb = 0; kb < 4; kb++) {
            uint32_t ah[4], al[4];
            split2(s[2 * kb][0],     s[2 * kb][1],     ah[0], al[0]);
            split2(s[2 * kb][2],     s[2 * kb][3],     ah[1], al[1]);
            split2(s[2 * kb + 1][0], s[2 * kb + 1][1], ah[2], al[2]);
            split2(s[2 * kb + 1][2], s[2 * kb + 1][3], ah[3], al[3]);
            #pragma unroll
            for (int nb = 0; nb < 4; nb++) {
                uint32_t vh[4], vl[4];
                uint32_t boff = (uint32_t)(((kb * 16 + l16) * AP + nb * 16 + hi8) * 2);
                ldsm_x4_trans(vh, vsHiB + boff);
                ldsm_x4_trans(vl, vsLoB + boff);
                mma_bf16(o[2 * nb],     ah, vh);
                mma_bf16(o[2 * nb + 1], ah, vh + 2);
                mma_bf16(o[2 * nb],     ah, vl);
                mma_bf16(o[2 * nb + 1], ah, vl + 2);
                mma_bf16(o[2 * nb],     al, vh);
                mma_bf16(o[2 * nb + 1], al, vh + 2);
            }
        }
        __syncthreads();
    }

    // ---- normalize + store ----
    float inv0 = 1.f / lS0, inv1 = 1.f / lS1;
    int rowA = b * SEQ + q0 + m0 + (lane >> 2);
    #pragma unroll
    for (int j = 0; j < 8; j++) {
        *reinterpret_cast<float2*>(out + (size_t)rowA * HEAD + j * 8 + c2) =
            make_float2(o[j][0] * inv0, o[j][1] * inv0);
        *reinterpret_cast<float2*>(out + (size_t)(rowA + 8) * HEAD + j * 8 + c2) =
            make_float2(o[j][2] * inv1, o[j][3] * inv1);
    }
}

// ---------------------------------------------------------------------------
extern "C" void kernel_launch(void* const* d_in, const int* in_sizes, int n_in,
                              void* d_out, int out_size)
{
    // bind by element count: 16777216 -> q,k,v ; 65536 -> Wq,Wk,Wv ; 16384 -> mask
    const void* big[3]   = {0, 0, 0};
    const void* small[3] = {0, 0, 0};
    const void* mk = 0;
    int nb = 0, ns = 0;
    for (int i = 0; i < n_in; i++) {
        if (in_sizes[i] == NROWS * DEMB)      { if (nb < 3) big[nb++] = d_in[i]; }
        else if (in_sizes[i] == DEMB * HEAD)  { if (ns < 3) small[ns++] = d_in[i]; }
        else if (in_sizes[i] == BATCH * SEQ)  { mk = d_in[i]; }
    }
    const float* q  = (const float*)big[0];
    const float* k  = (const float*)big[1];
    const float* v  = (const float*)big[2];
    const float* Wq = (const float*)small[0];
    const float* Wk = (const float*)small[1];
    const float* Wv = (const float*)small[2];
    const int*   mask = (const int*)mk;
    float* out = (float*)d_out;

    static bool attr_set = false;
    if (!attr_set) {
        cudaFuncSetAttribute(proj_mma_kernel, cudaFuncAttributeMaxDynamicSharedMemorySize, PROJ_SMEM);
        attr_set = true;
    }

    proj_mma_kernel<<<dim3(NROWS / 128, 3), 256, PROJ_SMEM>>>(q, k, v, Wq, Wk, Wv);
    attn_mma_kernel<<<dim3(SEQ / 64, BATCH), 128, ATTN_SMEM>>>(mask, out);
}

// round 6
// speedup vs baseline: 3.6429x; 1.0251x over previous
#include <cuda_runtime.h>
#include <cuda_bf16.h>
#include <cstdint>

// Problem constants (Head_84533546320520)
#define BATCH 8
#define SEQ   2048
#define DEMB  1024
#define HEAD  64
#define NROWS (BATCH * SEQ)   // 16384
#define SCALE 0.125f          // HEAD^-0.5

// Pre-split bf16 hi/lo scratch for projected q/k/v: [B*S, 64] each.
// q is pre-scaled by SCALE.
__device__ __nv_bfloat16 g_qh[NROWS * HEAD];
__device__ __nv_bfloat16 g_ql[NROWS * HEAD];
__device__ __nv_bfloat16 g_kh[NROWS * HEAD];
__device__ __nv_bfloat16 g_kl[NROWS * HEAD];
__device__ __nv_bfloat16 g_vh[NROWS * HEAD];
__device__ __nv_bfloat16 g_vl[NROWS * HEAD];

// ===========================================================================
// mma.sync / cp.async helpers (sm_80-era PTX; no sm_103a-gated features)
// ===========================================================================
__device__ __forceinline__ uint32_t smem_to_u32(const void* p) {
    uint32_t a;
    asm("{ .reg .u64 t; cvta.to.shared.u64 t, %1; cvt.u32.u64 %0, t; }"
        : "=r"(a) : "l"(p));
    return a;
}
__device__ __forceinline__ void ldsm_x4(uint32_t* r, uint32_t addr) {
    asm volatile("ldmatrix.sync.aligned.m8n8.x4.shared.b16 {%0,%1,%2,%3}, [%4];"
        : "=r"(r[0]), "=r"(r[1]), "=r"(r[2]), "=r"(r[3]) : "r"(addr));
}
__device__ __forceinline__ void ldsm_x4_trans(uint32_t* r, uint32_t addr) {
    asm volatile("ldmatrix.sync.aligned.m8n8.x4.trans.shared.b16 {%0,%1,%2,%3}, [%4];"
        : "=r"(r[0]), "=r"(r[1]), "=r"(r[2]), "=r"(r[3]) : "r"(addr));
}
__device__ __forceinline__ void mma_bf16(float* d, const uint32_t* a, const uint32_t* b) {
    asm volatile(
        "mma.sync.aligned.m16n8k16.row.col.f32.bf16.bf16.f32 "
        "{%0,%1,%2,%3}, {%4,%5,%6,%7}, {%8,%9}, {%0,%1,%2,%3};"
        : "+f"(d[0]), "+f"(d[1]), "+f"(d[2]), "+f"(d[3])
        : "r"(a[0]), "r"(a[1]), "r"(a[2]), "r"(a[3]), "r"(b[0]), "r"(b[1]));
}
__device__ __forceinline__ void split2(float x, float y, uint32_t& h, uint32_t& l) {
    __nv_bfloat162 hb = __float22bfloat162_rn(make_float2(x, y));
    float2 hf = __bfloat1622float2(hb);
    __nv_bfloat162 lb = __float22bfloat162_rn(make_float2(x - hf.x, y - hf.y));
    h = *reinterpret_cast<uint32_t*>(&hb);
    l = *reinterpret_cast<uint32_t*>(&lb);
}
__device__ __forceinline__ void cp_async16(uint32_t saddr, const void* gaddr) {
    asm volatile("cp.async.cg.shared.global [%0], [%1], 16;"
        :: "r"(saddr), "l"(gaddr) : "memory");
}
#define CP_COMMIT()  asm volatile("cp.async.commit_group;" ::: "memory")
#define CP_WAIT(n)   asm volatile("cp.async.wait_group %0;" :: "n"(n) : "memory")

// ===========================================================================
// Kernel 1: projections via mma.sync bf16 2-split. Epilogue stores SPLIT
// bf16 hi/lo to global (q pre-scaled by SCALE).
// grid = (NROWS/128, 3), block = 256.
// ===========================================================================
#define KC 64
#define NCH (DEMB / KC)          // 16
#define APAD 72
#define PROJ_SMEM ((2 * 128 * APAD + 2 * 64 * APAD) * 2)

__global__ __launch_bounds__(256) void proj_mma_kernel(
    const float* __restrict__ q, const float* __restrict__ k,
    const float* __restrict__ v,
    const float* __restrict__ Wq, const float* __restrict__ Wk,
    const float* __restrict__ Wv)
{
    extern __shared__ __align__(16) __nv_bfloat16 smb[];
    __nv_bfloat16* AsHi = smb;
    __nv_bfloat16* AsLo = AsHi + 128 * APAD;
    __nv_bfloat16* BsHi = AsLo + 128 * APAD;
    __nv_bfloat16* BsLo = BsHi + 64 * APAD;
    const uint32_t aHiB = smem_to_u32(AsHi);
    const uint32_t aLoB = smem_to_u32(AsLo);
    const uint32_t bHiB = smem_to_u32(BsHi);
    const uint32_t bLoB = smem_to_u32(BsLo);

    const int which = blockIdx.y;
    const float* __restrict__ X = (which == 0) ? q : (which == 1) ? k : v;
    const float* __restrict__ W = (which == 0) ? Wq : (which == 1) ? Wk : Wv;
    __nv_bfloat16* __restrict__ outH = (which == 0) ? g_qh : (which == 1) ? g_kh : g_vh;
    __nv_bfloat16* __restrict__ outL = (which == 0) ? g_ql : (which == 1) ? g_kl : g_vl;
    const float postmul = (which == 0) ? SCALE : 1.0f;

    const int tid = threadIdx.x;
    const int wid = tid >> 5;
    const int lane = tid & 31;
    const int l16 = lane & 15;
    const int hi8 = (lane >> 4) << 3;
    const int row0 = blockIdx.x * 128;
    const int m0 = wid * 16;

    float acc[8][4] = {};

    for (int c = 0; c < NCH; c++) {
        const int k0 = c * KC;
        if (c > 0) __syncthreads();

        #pragma unroll
        for (int i = 0; i < 8; i++) {
            int idx = tid + i * 256;
            int r   = idx >> 4;
            int cg  = idx & 15;
            float4 t = *reinterpret_cast<const float4*>(
                X + (size_t)(row0 + r) * DEMB + k0 + cg * 4);
            __nv_bfloat162 h01 = __float22bfloat162_rn(make_float2(t.x, t.y));
            __nv_bfloat162 h23 = __float22bfloat162_rn(make_float2(t.z, t.w));
            float2 f01 = __bfloat1622float2(h01);
            float2 f23 = __bfloat1622float2(h23);
            __nv_bfloat162 l01 = __float22bfloat162_rn(make_float2(t.x - f01.x, t.y - f01.y));
            __nv_bfloat162 l23 = __float22bfloat162_rn(make_float2(t.z - f23.x, t.w - f23.y));
            int o = r * APAD + cg * 4;
            *reinterpret_cast<__nv_bfloat162*>(&AsHi[o])     = h01;
            *reinterpret_cast<__nv_bfloat162*>(&AsHi[o + 2]) = h23;
            *reinterpret_cast<__nv_bfloat162*>(&AsLo[o])     = l01;
            *reinterpret_cast<__nv_bfloat162*>(&AsLo[o + 2]) = l23;
        }
        #pragma unroll
        for (int i = 0; i < 4; i++) {
            int idx = tid + i * 256;
            int kk  = idx >> 4;
            int ng  = idx & 15;
            float4 t = *reinterpret_cast<const float4*>(
                W + (size_t)(k0 + kk) * HEAD + ng * 4);
            __nv_bfloat162 h01 = __float22bfloat162_rn(make_float2(t.x, t.y));
            __nv_bfloat162 h23 = __float22bfloat162_rn(make_float2(t.z, t.w));
            float2 f01 = __bfloat1622float2(h01);
            float2 f23 = __bfloat1622float2(h23);
            __nv_bfloat162 l01 = __float22bfloat162_rn(make_float2(t.x - f01.x, t.y - f01.y));
            __nv_bfloat162 l23 = __float22bfloat162_rn(make_float2(t.z - f23.x, t.w - f23.y));
            int o = kk * APAD + ng * 4;
            *reinterpret_cast<__nv_bfloat162*>(&BsHi[o])     = h01;
            *reinterpret_cast<__nv_bfloat162*>(&BsHi[o + 2]) = h23;
            *reinterpret_cast<__nv_bfloat162*>(&BsLo[o])     = l01;
            *reinterpret_cast<__nv_bfloat162*>(&BsLo[o + 2]) = l23;
        }
        __syncthreads();

        #pragma unroll
        for (int kk = 0; kk < 4; kk++) {
            uint32_t a_hi[4], a_lo[4];
            uint32_t aoff = (uint32_t)(((m0 + l16) * APAD + kk * 16 + hi8) * 2);
            ldsm_x4(a_hi, aHiB + aoff);
            ldsm_x4(a_lo, aLoB + aoff);
            #pragma unroll
            for (int nb = 0; nb < 4; nb++) {
                uint32_t bh[4], bl[4];
                uint32_t boff = (uint32_t)(((kk * 16 + l16) * APAD + nb * 16 + hi8) * 2);
                ldsm_x4_trans(bh, bHiB + boff);
                ldsm_x4_trans(bl, bLoB + boff);
                mma_bf16(acc[2 * nb + 0], a_hi, bh + 0);
                mma_bf16(acc[2 * nb + 1], a_hi, bh + 2);
                mma_bf16(acc[2 * nb + 0], a_hi, bl + 0);
                mma_bf16(acc[2 * nb + 1], a_hi, bl + 2);
                mma_bf16(acc[2 * nb + 0], a_lo, bh + 0);
                mma_bf16(acc[2 * nb + 1], a_lo, bh + 2);
            }
        }
    }

    // epilogue: split fp32 acc -> bf16 hi/lo global (packed bf16x2 stores)
    const int r = lane >> 2;
    const int cc = (lane & 3) * 2;
    const size_t rA = (size_t)(row0 + m0 + r) * HEAD;
    const size_t rB = (size_t)(row0 + m0 + r + 8) * HEAD;
    #pragma unroll
    for (int j = 0; j < 8; j++) {
        uint32_t h, l;
        split2(acc[j][0] * postmul, acc[j][1] * postmul, h, l);
        *reinterpret_cast<uint32_t*>(&outH[rA + j * 8 + cc]) = h;
        *reinterpret_cast<uint32_t*>(&outL[rA + j * 8 + cc]) = l;
        split2(acc[j][2] * postmul, acc[j][3] * postmul, h, l);
        *reinterpret_cast<uint32_t*>(&outH[rB + j * 8 + cc]) = h;
        *reinterpret_cast<uint32_t*>(&outL[rB + j * 8 + cc]) = l;
    }
}

// ===========================================================================
// Kernel 2: flash attention, mma.sync bf16 2-split, cp.async double-buffered.
// grid = (SEQ/64, BATCH), block = 128 (4 warps).
// K/V arrive PRE-SPLIT from global; k-loop is pure copy + MMA.
// ===========================================================================
#define AP 72
#define BUFB (64 * AP * 2)            // 9216 bytes per 64x72 bf16 buffer
#define STAGEB (4 * BUFB)             // 36864 bytes: KsHi,KsLo,VsHi,VsLo
#define ATTN_SMEM (2 * STAGEB + 256)  // 73984 B
#define NT (SEQ / 64)                 // 32

__global__ __launch_bounds__(128) void attn_mma_kernel(
    const int* __restrict__ mask, float* __restrict__ out)
{
    extern __shared__ __align__(16) char smc[];
    const uint32_t smemB = smem_to_u32(smc);
    float* biasS = reinterpret_cast<float*>(smc + 2 * STAGEB);

    const int b  = blockIdx.y;
    const int q0 = blockIdx.x * 64;
    const size_t base = (size_t)b * SEQ * HEAD;

    const int tid  = threadIdx.x;
    const int wid  = tid >> 5;
    const int lane = tid & 31;
    const int l16  = lane & 15;
    const int hi8  = (lane >> 4) << 3;
    const int m0   = wid * 16;
    const int c2   = (lane & 3) * 2;

    // S-phase non-trans B-frag lane map on straight [key][h] (validated R5)
    const int krow = (lane & 7) + ((lane & 16) >> 1);
    const int hcol = (lane & 8);

    // ---- stage pre-split Q into stage-0 smem, extract A-frags ----
    {
        // QHi at bytes [0,BUFB), QLo at [BUFB,2*BUFB)
        #pragma unroll
        for (int i = 0; i < 4; i++) {
            int idx = tid + i * 128;          // 0..511
            int r = idx >> 3, cq = idx & 7;
            uint4 th = *reinterpret_cast<const uint4*>(g_qh + base + (size_t)(q0 + r) * HEAD + cq * 8);
            uint4 tl = *reinterpret_cast<const uint4*>(g_ql + base + (size_t)(q0 + r) * HEAD + cq * 8);
            *reinterpret_cast<uint4*>(smc + r * 144 + cq * 16)        = th;
            *reinterpret_cast<uint4*>(smc + BUFB + r * 144 + cq * 16) = tl;
        }
    }
    __syncthreads();
    uint32_t qh[4][4], qlr[4][4];
    #pragma unroll
    for (int kh = 0; kh < 4; kh++) {
        uint32_t aoff = (uint32_t)(((m0 + l16) * AP + kh * 16 + hi8) * 2);
        ldsm_x4(qh[kh],  smemB + aoff);
        ldsm_x4(qlr[kh], smemB + BUFB + aoff);
    }
    __syncthreads();   // Q frags extracted before cp.async overwrites stage 0

    // ---- prefetch tile 0 into stage 0 ----
    const __nv_bfloat16* srcs[4] = {g_kh + base, g_kl + base, g_vh + base, g_vl + base};
    {
        #pragma unroll
        for (int i = 0; i < 16; i++) {
            const int buf = i >> 2;
            int rem = tid + (i & 3) * 128;    // 0..511
            int r = rem >> 3, cq = rem & 7;
            cp_async16(smemB + buf * BUFB + r * 144 + cq * 16,
                       srcs[buf] + (size_t)r * HEAD + cq * 8);
        }
        CP_COMMIT();
    }

    const float NEG_INF = __int_as_float(0xff800000);
    float mR0 = NEG_INF, mR1 = NEG_INF, lS0 = 0.f, lS1 = 0.f;
    float o[8][4] = {};

    for (int kt = 0; kt < NT; kt++) {
        const int s = kt & 1;
        const uint32_t stB = smemB + s * STAGEB;

        // prefetch next tile into other stage
        if (kt + 1 < NT) {
            const int k1 = (kt + 1) * 64;
            const uint32_t st2 = smemB + ((kt + 1) & 1) * STAGEB;
            #pragma unroll
            for (int i = 0; i < 16; i++) {
                const int buf = i >> 2;
                int rem = tid + (i & 3) * 128;
                int r = rem >> 3, cq = rem & 7;
                cp_async16(st2 + buf * BUFB + r * 144 + cq * 16,
                           srcs[buf] + (size_t)(k1 + r) * HEAD + cq * 8);
            }
            CP_COMMIT();
            CP_WAIT(1);
        } else {
            CP_WAIT(0);
        }
        if (tid < 64)
            biasS[tid] = (mask[(size_t)b * SEQ + kt * 64 + tid] != 0) ? 0.f : -1e30f;
        __syncthreads();   // tile s + bias visible to all

        // ---- S = Q @ K^T ----
        float sF[8][4] = {};
        #pragma unroll
        for (int kh = 0; kh < 4; kh++) {
            #pragma unroll
            for (int nb = 0; nb < 4; nb++) {
                uint32_t bh[4], bl[4];
                uint32_t boff = (uint32_t)(((nb * 16 + krow) * AP + kh * 16 + hcol) * 2);
                ldsm_x4(bh, stB + boff);          // KsHi
                ldsm_x4(bl, stB + BUFB + boff);   // KsLo
                mma_bf16(sF[2 * nb],     qh[kh],  bh);
                mma_bf16(sF[2 * nb + 1], qh[kh],  bh + 2);
                mma_bf16(sF[2 * nb],     qh[kh],  bl);
                mma_bf16(sF[2 * nb + 1], qh[kh],  bl + 2);
                mma_bf16(sF[2 * nb],     qlr[kh], bh);
                mma_bf16(sF[2 * nb + 1], qlr[kh], bh + 2);
            }
        }

        // ---- online softmax on C-frags ----
        float mx0 = NEG_INF, mx1 = NEG_INF;
        #pragma unroll
        for (int j = 0; j < 8; j++) {
            float2 bv = *reinterpret_cast<float2*>(&biasS[j * 8 + c2]);
            sF[j][0] += bv.x; sF[j][1] += bv.y; sF[j][2] += bv.x; sF[j][3] += bv.y;
            mx0 = fmaxf(mx0, fmaxf(sF[j][0], sF[j][1]));
            mx1 = fmaxf(mx1, fmaxf(sF[j][2], sF[j][3]));
        }
        mx0 = fmaxf(mx0, __shfl_xor_sync(0xffffffffu, mx0, 1));
        mx0 = fmaxf(mx0, __shfl_xor_sync(0xffffffffu, mx0, 2));
        mx1 = fmaxf(mx1, __shfl_xor_sync(0xffffffffu, mx1, 1));
        mx1 = fmaxf(mx1, __shfl_xor_sync(0xffffffffu, mx1, 2));
        float mn0 = fmaxf(mR0, mx0), mn1 = fmaxf(mR1, mx1);
        float a0 = __expf(mR0 - mn0), a1 = __expf(mR1 - mn1);
        float sm0 = 0.f, sm1 = 0.f;
        #pragma unroll
        for (int j = 0; j < 8; j++) {
            sF[j][0] = __expf(sF[j][0] - mn0);
            sF[j][1] = __expf(sF[j][1] - mn0);
            sF[j][2] = __expf(sF[j][2] - mn1);
            sF[j][3] = __expf(sF[j][3] - mn1);
            sm0 += sF[j][0] + sF[j][1];
            sm1 += sF[j][2] + sF[j][3];
        }
        sm0 += __shfl_xor_sync(0xffffffffu, sm0, 1);
        sm0 += __shfl_xor_sync(0xffffffffu, sm0, 2);
        sm1 += __shfl_xor_sync(0xffffffffu, sm1, 1);
        sm1 += __shfl_xor_sync(0xffffffffu, sm1, 2);
        lS0 = lS0 * a0 + sm0; lS1 = lS1 * a1 + sm1;
        mR0 = mn0; mR1 = mn1;
        #pragma unroll
        for (int j = 0; j < 8; j++) {
            o[j][0] *= a0; o[j][1] *= a0; o[j][2] *= a1; o[j][3] *= a1;
        }

        // ---- O += P @ V  (P frags built in-register) ----
        #pragma unroll
        for (int kb = 0; kb < 4; kb++) {
            uint32_t ah[4], al[4];
            split2(sF[2 * kb][0],     sF[2 * kb][1],     ah[0], al[0]);
            split2(sF[2 * kb][2],     sF[2 * kb][3],     ah[1], al[1]);
            split2(sF[2 * kb + 1][0], sF[2 * kb + 1][1], ah[2], al[2]);
            split2(sF[2 * kb + 1][2], sF[2 * kb + 1][3], ah[3], al[3]);
            #pragma unroll
            for (int nb = 0; nb < 4; nb++) {
                uint32_t vh[4], vl[4];
                uint32_t boff = (uint32_t)(((kb * 16 + l16) * AP + nb * 16 + hi8) * 2);
                ldsm_x4_trans(vh, stB + 2 * BUFB + boff);   // VsHi
                ldsm_x4_trans(vl, stB + 3 * BUFB + boff);   // VsLo
                mma_bf16(o[2 * nb],     ah, vh);
                mma_bf16(o[2 * nb + 1], ah, vh + 2);
                mma_bf16(o[2 * nb],     ah, vl);
                mma_bf16(o[2 * nb + 1], ah, vl + 2);
                mma_bf16(o[2 * nb],     al, vh);
                mma_bf16(o[2 * nb + 1], al, vh + 2);
            }
        }
        __syncthreads();   // stage-s reads done before it's refilled (iter kt+1's cp.async)
    }

    // ---- normalize + store ----
    float inv0 = 1.f / lS0, inv1 = 1.f / lS1;
    int rowA = b * SEQ + q0 + m0 + (lane >> 2);
    #pragma unroll
    for (int j = 0; j < 8; j++) {
        *reinterpret_cast<float2*>(out + (size_t)rowA * HEAD + j * 8 + c2) =
            make_float2(o[j][0] * inv0, o[j][1] * inv0);
        *reinterpret_cast<float2*>(out + (size_t)(rowA + 8) * HEAD + j * 8 + c2) =
            make_float2(o[j][2] * inv1, o[j][3] * inv1);
    }
}

// ---------------------------------------------------------------------------
extern "C" void kernel_launch(void* const* d_in, const int* in_sizes, int n_in,
                              void* d_out, int out_size)
{
    // bind by element count: 16777216 -> q,k,v ; 65536 -> Wq,Wk,Wv ; 16384 -> mask
    const void* big[3]   = {0, 0, 0};
    const void* small[3] = {0, 0, 0};
    const void* mk = 0;
    int nb = 0, ns = 0;
    for (int i = 0; i < n_in; i++) {
        if (in_sizes[i] == NROWS * DEMB)      { if (nb < 3) big[nb++] = d_in[i]; }
        else if (in_sizes[i] == DEMB * HEAD)  { if (ns < 3) small[ns++] = d_in[i]; }
        else if (in_sizes[i] == BATCH * SEQ)  { mk = d_in[i]; }
    }
    const float* q  = (const float*)big[0];
    const float* k  = (const float*)big[1];
    const float* v  = (const float*)big[2];
    const float* Wq = (const float*)small[0];
    const float* Wk = (const float*)small[1];
    const float* Wv = (const float*)small[2];
    const int*   mask = (const int*)mk;
    float* out = (float*)d_out;

    static bool attr_set = false;
    if (!attr_set) {
        cudaFuncSetAttribute(proj_mma_kernel, cudaFuncAttributeMaxDynamicSharedMemorySize, PROJ_SMEM);
        cudaFuncSetAttribute(attn_mma_kernel, cudaFuncAttributeMaxDynamicSharedMemorySize, ATTN_SMEM);
        attr_set = true;
    }

    proj_mma_kernel<<<dim3(NROWS / 128, 3), 256, PROJ_SMEM>>>(q, k, v, Wq, Wk, Wv);
    attn_mma_kernel<<<dim3(SEQ / 64, BATCH), 128, ATTN_SMEM>>>(mask, out);
}